// round 6
// baseline (speedup 1.0000x reference)
#include <cuda_runtime.h>

// Problem constants
#define B_   8
#define C_   32      // Cin == Cout == 32
#define H_   224
#define W_   224
#define HP_  226     // padded
#define WP_  226
#define NW_  8       // 32 channels / 4 per dp4a word

// -------- device-global scratch (no allocations allowed) --------
__device__ unsigned g_xmax_bits;
__device__ unsigned g_wmax_bits;
__device__ float    g_scale;    // x_scale * w_scale
__device__ float    g_xscale;   // x_scale
// weights packed [tap][cg][co]: word at (tap*8+cg)*32+co, byte k = qw[co][4*cg+k][tap]
__device__ __align__(16) int g_qw[9 * NW_ * C_];
// padded NHWC, packed s8x4: word at ((b*HP_+hp)*WP_+wp)*8 + cg
__device__ __align__(16) int g_xq[B_ * HP_ * WP_ * NW_];

// -------- 0: reset x-max accumulator AND fully reduce max|w| (no x dependency) --------
__global__ void k_prep(const float* __restrict__ w, int n) {
    __shared__ float s_red[8];
    if (threadIdx.x == 0) g_xmax_bits = 0u;   // visible to k_xmax via launch ordering
    float m = 0.f;
    for (int i = threadIdx.x; i < n; i += blockDim.x)
        m = fmaxf(m, fabsf(w[i]));
#pragma unroll
    for (int o = 16; o; o >>= 1)
        m = fmaxf(m, __shfl_xor_sync(0xFFFFFFFFu, m, o));
    if ((threadIdx.x & 31) == 0) s_red[threadIdx.x >> 5] = m;
    __syncthreads();
    if (threadIdx.x == 0) {
        float r = s_red[0];
#pragma unroll
        for (int k = 1; k < 8; k++) r = fmaxf(r, s_red[k]);
        g_wmax_bits = __float_as_uint(r);
    }
}

// -------- 1: max|x| over 12.8M floats --------
__global__ void k_xmax(const float4* __restrict__ x, int n4) {
    float m = 0.f;
    for (int i = blockIdx.x * blockDim.x + threadIdx.x; i < n4;
         i += gridDim.x * blockDim.x) {
        float4 v = x[i];
        m = fmaxf(m, fmaxf(fmaxf(fabsf(v.x), fabsf(v.y)),
                           fmaxf(fabsf(v.z), fabsf(v.w))));
    }
#pragma unroll
    for (int o = 16; o; o >>= 1)
        m = fmaxf(m, __shfl_xor_sync(0xFFFFFFFFu, m, o));
    if ((threadIdx.x & 31) == 0)
        atomicMax(&g_xmax_bits, __float_as_uint(m));  // m >= 0: bits monotone
}

// -------- 2: quantize + pack weights [tap][cg][co], publish scales --------
__global__ void k_qw(const float* __restrict__ wgt) {
    float wmax = __uint_as_float(g_wmax_bits);
    float xmax = __uint_as_float(g_xmax_bits);
    float ws = __fdiv_rn(wmax, 127.0f);   // match jnp: max/qmax, IEEE divide
    float xs = __fdiv_rn(xmax, 127.0f);
    if (threadIdx.x == 0) {
        g_scale  = xs * ws;   // reference multiplies (x_scale * w_scale) first
        g_xscale = xs;
    }
    for (int idx = threadIdx.x; idx < 9 * NW_ * C_; idx += blockDim.x) {
        int co  = idx & 31;
        int cg  = (idx >> 5) & 7;
        int tap = idx / (NW_ * C_);
        int ki = tap / 3, kj = tap % 3;
        int word = 0;
#pragma unroll
        for (int k = 0; k < 4; k++) {
            float v = wgt[((co * C_ + cg * 4 + k) * 3 + ki) * 3 + kj];
            int q = (int)rintf(__fdiv_rn(v, ws));   // round-half-even like jnp.round
            q = max(-127, min(127, q));
            word |= (q & 0xFF) << (8 * k);
        }
        g_qw[idx] = word;
    }
}

// -------- 3: quantize x into padded NHWC int8, one block per (b,h) row.
// Blocks at h==0 / h==H_-1 also zero the adjacent full padded row.
__global__ void __launch_bounds__(W_) k_qx(const float* __restrict__ x) {
    int b = blockIdx.x / H_;
    int h = blockIdx.x - b * H_;
    int w = threadIdx.x;           // 0..223
    float xs = g_xscale;

    const float* px = x + ((b * C_) * H_ + h) * W_ + w;
    int word[NW_];
#pragma unroll
    for (int cg = 0; cg < NW_; cg++) {
        int wd = 0;
#pragma unroll
        for (int k = 0; k < 4; k++) {
            float v = px[(cg * 4 + k) * H_ * W_];   // coalesced across threads
            int q = (int)rintf(__fdiv_rn(v, xs));
            q = max(-127, min(127, q));
            wd |= (q & 0xFF) << (8 * k);
        }
        word[cg] = wd;
    }
    // store packed row at padded coords (h+1, w+1): 2 x int4, coalesced
    int4* dst = (int4*)(g_xq + ((b * HP_ + h + 1) * WP_ + (w + 1)) * NW_);
    dst[0] = make_int4(word[0], word[1], word[2], word[3]);
    dst[1] = make_int4(word[4], word[5], word[6], word[7]);
    // left/right column pad for this row
    if (w < 2) {
        int wp = (w == 0) ? 0 : (WP_ - 1);
        int4* pz = (int4*)(g_xq + ((b * HP_ + h + 1) * WP_ + wp) * NW_);
        pz[0] = make_int4(0, 0, 0, 0);
        pz[1] = make_int4(0, 0, 0, 0);
    }
    // fused top/bottom pad rows
    if (h == 0 || h == H_ - 1) {
        int hp = (h == 0) ? 0 : (HP_ - 1);
        int4* pr = (int4*)(g_xq + (b * HP_ + hp) * WP_ * NW_);
        const int row4 = (WP_ * NW_) / 4;   // 452 int4 per padded row
        for (int i = w; i < row4; i += W_)
            pr[i] = make_int4(0, 0, 0, 0);
    }
}

// -------- 4: dp4a conv, one block per (b,h) output row --------
// smem x swizzle: word (pix,cg) at pix*8 + (pix>>2)*4 + cg (16B-aligned per quad).
// 8-lane LDS.128 phase over pixels p..p+7 starts at bank-quads
// {0,8,16,24,4,12,20,28}: all 32 banks exactly once -> conflict-free.
// (56 % 8 == 0, so the wt wrap 55->0 preserves consecutive pix mod 8.)
#define ROW_WORDS 2036   // max addr = 225*8 + 56*4 + 4 + 3 = 2031; pad to %4==0

__global__ void __launch_bounds__(224, 3) k_conv(const float* __restrict__ bias,
                                                 float* __restrict__ out) {
    __shared__ __align__(16) int s_x[3 * ROW_WORDS];
    __shared__ __align__(16) int s_w[9 * NW_ * C_];
    __shared__ float s_bias[C_];

    int tid = threadIdx.x;
    int b = blockIdx.x / H_;
    int h = blockIdx.x - b * H_;

    // weights: 576 int4, coalesced
    {
        const int4* wsrc = (const int4*)g_qw;
        int4* wdst = (int4*)s_w;
        for (int i = tid; i < (9 * NW_ * C_) / 4; i += 224) wdst[i] = wsrc[i];
    }
    if (tid < C_) s_bias[tid] = bias[tid];

    // load 3 padded input rows (h, h+1, h+2 in padded coords), int4 both sides.
    // int4 index i4 within a row: pix = i4>>1, half = i4&1;
    // swizzled word addr = pix*8 + (pix>>2)*4 + half*4 (16B aligned).
    {
        const int4* src = (const int4*)(g_xq + (b * HP_ + h) * WP_ * NW_);
        const int row4 = (WP_ * NW_) / 4;              // 452 int4 per row
        for (int i = tid; i < 3 * row4; i += 224) {
            int r  = i / row4;
            int i4 = i - r * row4;
            int pix = i4 >> 1, half = i4 & 1;
            *(int4*)(s_x + r * ROW_WORDS + pix * 8 + (pix >> 2) * 4 + half * 4) =
                src[i];
        }
    }
    __syncthreads();

    int wt     = tid % 56;          // outputs wt, wt+56, wt+112, wt+168
    int cobase = (tid / 56) * 8;    // 8 consecutive output channels

    int acc[4][8];
#pragma unroll
    for (int jj = 0; jj < 4; jj++)
#pragma unroll
        for (int r = 0; r < 8; r++) acc[jj][r] = 0;

#pragma unroll
    for (int ki = 0; ki < 3; ki++) {
        const int* xr = s_x + ki * ROW_WORDS;
#pragma unroll
        for (int kj = 0; kj < 3; kj++) {
            const int* wt_base = s_w + (ki * 3 + kj) * NW_ * C_ + cobase;
#pragma unroll
            for (int half = 0; half < 2; half++) {
                int4 xh[4];
#pragma unroll
                for (int jj = 0; jj < 4; jj++) {
                    int pix = wt + 56 * jj + kj;
                    xh[jj] = *(const int4*)(xr + pix * 8 + (pix >> 2) * 4 + half * 4);
                }
#pragma unroll
                for (int cg4 = 0; cg4 < 4; cg4++) {
                    const int* wr = wt_base + (half * 4 + cg4) * C_;
                    int4 wa = *(const int4*)(wr);       // co 0..3 (near-broadcast)
                    int4 wb = *(const int4*)(wr + 4);   // co 4..7
#pragma unroll
                    for (int jj = 0; jj < 4; jj++) {
                        int xw = (cg4 == 0) ? xh[jj].x : (cg4 == 1) ? xh[jj].y
                               : (cg4 == 2) ? xh[jj].z : xh[jj].w;
                        acc[jj][0] = __dp4a(xw, wa.x, acc[jj][0]);
                        acc[jj][1] = __dp4a(xw, wa.y, acc[jj][1]);
                        acc[jj][2] = __dp4a(xw, wa.z, acc[jj][2]);
                        acc[jj][3] = __dp4a(xw, wa.w, acc[jj][3]);
                        acc[jj][4] = __dp4a(xw, wb.x, acc[jj][4]);
                        acc[jj][5] = __dp4a(xw, wb.y, acc[jj][5]);
                        acc[jj][6] = __dp4a(xw, wb.z, acc[jj][6]);
                        acc[jj][7] = __dp4a(xw, wb.w, acc[jj][7]);
                    }
                }
            }
        }
    }

    // dequantize + bias, NCHW store (coalesced: warp spans contiguous w)
    float sc = g_scale;
    float* ob = out + ((b * C_ + cobase) * H_ + h) * W_;
#pragma unroll
    for (int r = 0; r < 8; r++) {
        float bb = s_bias[cobase + r];
        float* po = ob + r * H_ * W_;
#pragma unroll
        for (int jj = 0; jj < 4; jj++)
            po[wt + 56 * jj] = (float)acc[jj][r] * sc + bb;
    }
}

// -------- launch --------
extern "C" void kernel_launch(void* const* d_in, const int* in_sizes, int n_in,
                              void* d_out, int out_size) {
    const float* x    = (const float*)d_in[0];   // [8,32,224,224]
    const float* w    = (const float*)d_in[1];   // [32,32,3,3]
    const float* bias = (const float*)d_in[2];   // [32]
    float* out = (float*)d_out;                  // [8,32,224,224]

    k_prep<<<1, 256>>>(w, C_ * C_ * 9);          // zero xmax acc + reduce wmax

    int n4 = (B_ * C_ * H_ * W_) / 4;            // exactly divisible
    k_xmax<<<1024, 256>>>((const float4*)x, n4);
    k_qw<<<1, 256>>>(w);

    k_qx<<<B_ * H_, W_>>>(x);

    k_conv<<<B_ * H_, 224>>>(bias, out);
}

// round 11
// speedup vs baseline: 1.1831x; 1.1831x over previous
#include <cuda_runtime.h>
#include <cstdint>

// Problem constants
#define B_   8
#define C_   32      // Cin == Cout == 32
#define H_   224
#define W_   224
#define HP_  226     // padded
#define WP_  226
#define NW_  8       // 32 channels / 4 packed int8 per word

// -------- device-global scratch (no allocations allowed) --------
__device__ unsigned g_xmax_bits;
__device__ unsigned g_wmax_bits;
// B fragments in mma layout: [tap][nt][lane] -> int2 {b0, b1}
//   b0 byte kk = qw[co = nt*8 + lane/4][ch = 4*(lane%4) + kk][tap]
//   b1 byte kk = qw[co]              [ch = 16 + 4*(lane%4) + kk][tap]
__device__ __align__(16) int2 g_qwm[9 * 4 * 32];
// padded NHWC, packed s8x4: word at ((b*HP_+hp)*WP_+wp)*8 + cg
__device__ __align__(16) int g_xq[B_ * HP_ * WP_ * NW_];

// -------- 0: zero xmax acc + reduce max|w| + pack B fragments --------
__global__ void k_prepqw(const float* __restrict__ wgt, int n) {
    __shared__ float s_red[8];
    __shared__ float s_ws;
    if (threadIdx.x == 0) g_xmax_bits = 0u;
    float m = 0.f;
    for (int i = threadIdx.x; i < n; i += blockDim.x)
        m = fmaxf(m, fabsf(wgt[i]));
#pragma unroll
    for (int o = 16; o; o >>= 1)
        m = fmaxf(m, __shfl_xor_sync(0xFFFFFFFFu, m, o));
    if ((threadIdx.x & 31) == 0) s_red[threadIdx.x >> 5] = m;
    __syncthreads();
    if (threadIdx.x == 0) {
        float r = s_red[0];
#pragma unroll
        for (int k = 1; k < 8; k++) r = fmaxf(r, s_red[k]);
        g_wmax_bits = __float_as_uint(r);
        s_ws = __fdiv_rn(r, 127.0f);   // match jnp: max/qmax, IEEE divide
    }
    __syncthreads();
    float ws = s_ws;
    for (int idx = threadIdx.x; idx < 9 * 4 * 32; idx += blockDim.x) {
        int lane = idx & 31;
        int nt   = (idx >> 5) & 3;
        int tap  = idx >> 7;
        int ki = tap / 3, kj = tap % 3;
        int co = nt * 8 + (lane >> 2);
        int cb = (lane & 3) * 4;
        int w0 = 0, w1 = 0;
#pragma unroll
        for (int kk = 0; kk < 4; kk++) {
            float v0 = wgt[((co * C_ + (cb + kk)) * 3 + ki) * 3 + kj];
            float v1 = wgt[((co * C_ + (16 + cb + kk)) * 3 + ki) * 3 + kj];
            int q0 = (int)rintf(__fdiv_rn(v0, ws));   // round-half-even
            int q1 = (int)rintf(__fdiv_rn(v1, ws));
            q0 = max(-127, min(127, q0));
            q1 = max(-127, min(127, q1));
            w0 |= (q0 & 0xFF) << (8 * kk);
            w1 |= (q1 & 0xFF) << (8 * kk);
        }
        g_qwm[idx] = make_int2(w0, w1);
    }
}

// -------- 1: max|x| over 12.8M floats, 4x unrolled batched loads --------
__global__ void k_xmax(const float4* __restrict__ x, int n4) {
    int stride = gridDim.x * blockDim.x;
    int i = blockIdx.x * blockDim.x + threadIdx.x;
    float m0 = 0.f, m1 = 0.f, m2 = 0.f, m3 = 0.f;
    for (; i + 3 * stride < n4; i += 4 * stride) {
        float4 a = x[i];
        float4 b = x[i + stride];
        float4 c = x[i + 2 * stride];
        float4 d = x[i + 3 * stride];
        m0 = fmaxf(m0, fmaxf(fmaxf(fabsf(a.x), fabsf(a.y)),
                             fmaxf(fabsf(a.z), fabsf(a.w))));
        m1 = fmaxf(m1, fmaxf(fmaxf(fabsf(b.x), fabsf(b.y)),
                             fmaxf(fabsf(b.z), fabsf(b.w))));
        m2 = fmaxf(m2, fmaxf(fmaxf(fabsf(c.x), fabsf(c.y)),
                             fmaxf(fabsf(c.z), fabsf(c.w))));
        m3 = fmaxf(m3, fmaxf(fmaxf(fabsf(d.x), fabsf(d.y)),
                             fmaxf(fabsf(d.z), fabsf(d.w))));
    }
    for (; i < n4; i += stride) {
        float4 a = x[i];
        m0 = fmaxf(m0, fmaxf(fmaxf(fabsf(a.x), fabsf(a.y)),
                             fmaxf(fabsf(a.z), fabsf(a.w))));
    }
    float m = fmaxf(fmaxf(m0, m1), fmaxf(m2, m3));
#pragma unroll
    for (int o = 16; o; o >>= 1)
        m = fmaxf(m, __shfl_xor_sync(0xFFFFFFFFu, m, o));
    if ((threadIdx.x & 31) == 0)
        atomicMax(&g_xmax_bits, __float_as_uint(m));  // m >= 0: bits monotone
}

// -------- 2: quantize x into padded NHWC int8, one block per (b,h) row.
// ALL 32 channel loads front-batched into registers (MLP=32) before arithmetic
// (the cg-interleaved version measured 34.5us latency-bound at 28 regs).
__global__ void __launch_bounds__(W_) k_qx(const float* __restrict__ x) {
    int b = blockIdx.x / H_;
    int h = blockIdx.x - b * H_;
    int w = threadIdx.x;           // 0..223
    float xs = __fdiv_rn(__uint_as_float(g_xmax_bits), 127.0f);

    const float* px = x + ((b * C_) * H_ + h) * W_ + w;
    float v[C_];
#pragma unroll
    for (int c = 0; c < C_; c++)
        v[c] = px[c * H_ * W_];    // 32 independent coalesced LDGs

    int word[NW_];
#pragma unroll
    for (int cg = 0; cg < NW_; cg++) {
        int wd = 0;
#pragma unroll
        for (int k = 0; k < 4; k++) {
            int q = (int)rintf(__fdiv_rn(v[cg * 4 + k], xs));
            q = max(-127, min(127, q));
            wd |= (q & 0xFF) << (8 * k);
        }
        word[cg] = wd;
    }
    int4* dst = (int4*)(g_xq + ((b * HP_ + h + 1) * WP_ + (w + 1)) * NW_);
    dst[0] = make_int4(word[0], word[1], word[2], word[3]);
    dst[1] = make_int4(word[4], word[5], word[6], word[7]);
    if (w < 2) {
        int wp = (w == 0) ? 0 : (WP_ - 1);
        int4* pz = (int4*)(g_xq + ((b * HP_ + h + 1) * WP_ + wp) * NW_);
        pz[0] = make_int4(0, 0, 0, 0);
        pz[1] = make_int4(0, 0, 0, 0);
    }
    if (h == 0 || h == H_ - 1) {
        int hp = (h == 0) ? 0 : (HP_ - 1);
        int4* pr = (int4*)(g_xq + (b * HP_ + hp) * WP_ * NW_);
        const int row4 = (WP_ * NW_) / 4;
        for (int i = w; i < row4; i += W_)
            pr[i] = make_int4(0, 0, 0, 0);
    }
}

// -------- mma helpers --------
__device__ __forceinline__ void ldsm_x4(uint32_t* r, uint32_t saddr) {
    asm volatile(
        "ldmatrix.sync.aligned.m8n8.x4.shared.b16 {%0,%1,%2,%3}, [%4];"
        : "=r"(r[0]), "=r"(r[1]), "=r"(r[2]), "=r"(r[3]) : "r"(saddr));
}
__device__ __forceinline__ void mma_s8(int* d, const uint32_t* a,
                                       uint32_t b0, uint32_t b1) {
    asm volatile(
        "mma.sync.aligned.m16n8k32.row.col.s32.s8.s8.s32 "
        "{%0,%1,%2,%3}, {%4,%5,%6,%7}, {%8,%9}, {%0,%1,%2,%3};"
        : "+r"(d[0]), "+r"(d[1]), "+r"(d[2]), "+r"(d[3])
        : "r"(a[0]), "r"(a[1]), "r"(a[2]), "r"(a[3]), "r"(b0), "r"(b1));
}

// -------- 3: IMMA conv, one block per (b,h) output row --------
// GEMM: M=224 pixels (14x16-tiles, 2 per warp), N=32 co (4x8), K=288 (9 taps x 32ch).
// smem x swizzle: word (pix,cg) at pix*8 + (pix>>2)*4 + cg; each pixel row is two
// 16B chunks (ch 0-15, ch 16-31) -> ldmatrix.x4 tiles. 8 consecutive pixels start
// at bank-quads {0,8,16,24,4,12,20,28}: conflict-free for every phase/shift.
#define ROW_WORDS 2036   // max swizzled word = 2031; pad to %4==0

__global__ void __launch_bounds__(224, 2) k_conv(const float* __restrict__ bias,
                                                 float* __restrict__ out) {
    __shared__ __align__(16) int  s_x[3 * ROW_WORDS];
    __shared__ __align__(16) int2 s_wm[9 * 4 * 32];
    __shared__ float s_bias[C_];

    int tid = threadIdx.x;
    int b = blockIdx.x / H_;
    int h = blockIdx.x - b * H_;
    int wid  = tid >> 5;
    int lane = tid & 31;

    // B fragments: 576 int4, coalesced
    {
        const int4* wsrc = (const int4*)g_qwm;
        int4* wdst = (int4*)s_wm;
        for (int i = tid; i < (9 * 4 * 32 * 2) / 4; i += 224) wdst[i] = wsrc[i];
    }
    if (tid < C_) s_bias[tid] = bias[tid];

    // load 3 padded input rows (h, h+1, h+2 in padded coords), int4 both sides
    {
        const int4* src = (const int4*)(g_xq + (b * HP_ + h) * WP_ * NW_);
        const int row4 = (WP_ * NW_) / 4;              // 452 int4 per row
        for (int i = tid; i < 3 * row4; i += 224) {
            int r  = i / row4;
            int i4 = i - r * row4;
            int pix = i4 >> 1, half = i4 & 1;
            *(int4*)(s_x + r * ROW_WORDS + pix * 8 + (pix >> 2) * 4 + half * 4) =
                src[i];
        }
    }
    __syncthreads();

    // ldmatrix lane addresses: matrix i takes its 8 row addrs from lanes 8i..8i+7.
    // grp0: pix 0-7 / ch 0-15 (-> a0), grp1: pix 8-15 / ch 0-15 (a1),
    // grp2: pix 0-7 / ch16-31 (a2), grp3: pix 8-15 / ch16-31 (a3).
    uint32_t sx_base = (uint32_t)__cvta_generic_to_shared(s_x);
    int grp  = lane >> 3;
    int row8 = lane & 7;
    int half = grp >> 1;
    int rofs = (grp & 1) << 3;
    uint32_t a_addr[2][3];
#pragma unroll
    for (int mt = 0; mt < 2; mt++) {
#pragma unroll
        for (int kj = 0; kj < 3; kj++) {
            int pix = 32 * wid + 16 * mt + kj + row8 + rofs;
            int word = pix * 8 + (pix >> 2) * 4 + half * 4;
            a_addr[mt][kj] = sx_base + word * 4;
        }
    }

    int acc[2][4][4];
#pragma unroll
    for (int mt = 0; mt < 2; mt++)
#pragma unroll
        for (int nt = 0; nt < 4; nt++)
#pragma unroll
            for (int r = 0; r < 4; r++) acc[mt][nt][r] = 0;

#pragma unroll
    for (int ki = 0; ki < 3; ki++) {
        uint32_t kofs = ki * (ROW_WORDS * 4);
#pragma unroll
        for (int kj = 0; kj < 3; kj++) {
            int tap = ki * 3 + kj;
            // batch the 4 B-fragment LDS.64s so their latency overlaps ldsm/mma
            int2 bf[4];
#pragma unroll
            for (int nt = 0; nt < 4; nt++)
                bf[nt] = s_wm[(tap * 4 + nt) * 32 + lane];
            uint32_t A0[4], A1[4];
            ldsm_x4(A0, a_addr[0][kj] + kofs);
            ldsm_x4(A1, a_addr[1][kj] + kofs);
#pragma unroll
            for (int nt = 0; nt < 4; nt++) {
                mma_s8(acc[0][nt], A0, (uint32_t)bf[nt].x, (uint32_t)bf[nt].y);
                mma_s8(acc[1][nt], A1, (uint32_t)bf[nt].x, (uint32_t)bf[nt].y);
            }
        }
    }

    // dequantize + bias, NCHW store.
    // c-fragment: c0 (pix = base + lane/4, co = nt*8 + (lane%4)*2), c1 co+1,
    // c2/c3 pix+8. Fixed lane%4 -> 8 consecutive pixels: full 32B sectors.
    float xs = __fdiv_rn(__uint_as_float(g_xmax_bits), 127.0f);
    float ws = __fdiv_rn(__uint_as_float(g_wmax_bits), 127.0f);
    float sc = xs * ws;
#pragma unroll
    for (int mt = 0; mt < 2; mt++) {
        int pix0 = 32 * wid + 16 * mt + (lane >> 2);
#pragma unroll
        for (int nt = 0; nt < 4; nt++) {
            int co0 = nt * 8 + (lane & 3) * 2;
            float b0f = s_bias[co0], b1f = s_bias[co0 + 1];
            float* o00 = out + ((b * C_ + co0) * H_ + h) * W_;
            float* o01 = o00 + H_ * W_;
            o00[pix0]     = (float)acc[mt][nt][0] * sc + b0f;
            o01[pix0]     = (float)acc[mt][nt][1] * sc + b1f;
            o00[pix0 + 8] = (float)acc[mt][nt][2] * sc + b0f;
            o01[pix0 + 8] = (float)acc[mt][nt][3] * sc + b1f;
        }
    }
}

// -------- launch --------
extern "C" void kernel_launch(void* const* d_in, const int* in_sizes, int n_in,
                              void* d_out, int out_size) {
    const float* x    = (const float*)d_in[0];   // [8,32,224,224]
    const float* w    = (const float*)d_in[1];   // [32,32,3,3]
    const float* bias = (const float*)d_in[2];   // [32]
    float* out = (float*)d_out;                  // [8,32,224,224]

    k_prepqw<<<1, 256>>>(w, C_ * C_ * 9);        // zero xmax + wmax + pack B frags

    int n4 = (B_ * C_ * H_ * W_) / 4;            // exactly divisible
    k_xmax<<<1184, 256>>>((const float4*)x, n4); // 148 SMs x 8: exact waves

    k_qx<<<B_ * H_, W_>>>(x);

    k_conv<<<B_ * H_, 224>>>(bias, out);
}

// round 17
// speedup vs baseline: 1.2924x; 1.0924x over previous
#include <cuda_runtime.h>
#include <cstdint>

// Problem constants
#define B_   8
#define C_   32      // Cin == Cout == 32
#define H_   224
#define W_   224
#define HP_  226     // padded
#define WP_  226
#define NW_  8       // 32 channels / 4 packed int8 per word

// -------- device-global scratch (no allocations allowed) --------
__device__ unsigned g_xmax_bits;
__device__ unsigned g_wmax_bits;
// mma B fragments (co 0-15): [tap][nt2][lane] -> int2 {b0, b1}
//   b0 byte kk = qw[co = nt2*8 + lane/4][ch = 4*(lane%4) + kk][tap]
//   b1 byte kk = qw[co]                [ch = 16 + 4*(lane%4) + kk][tap]
__device__ __align__(16) int2 g_qwm[9 * 2 * 32];
// dp4a weights (co 16-31): word at (tap*8+cg)*16 + (co-16), byte k = qw[co][4cg+k][tap]
__device__ __align__(16) int  g_qwd[9 * 8 * 16];
// padded NHWC, packed s8x4: word at ((b*HP_+hp)*WP_+wp)*8 + cg
__device__ __align__(16) int g_xq[B_ * HP_ * WP_ * NW_];

// -------- 0: zero xmax acc + reduce max|w| + pack both weight layouts --------
__global__ void k_prepqw(const float* __restrict__ wgt, int n) {
    __shared__ float s_red[8];
    __shared__ float s_ws;
    if (threadIdx.x == 0) g_xmax_bits = 0u;
    float m = 0.f;
    for (int i = threadIdx.x; i < n; i += blockDim.x)
        m = fmaxf(m, fabsf(wgt[i]));
#pragma unroll
    for (int o = 16; o; o >>= 1)
        m = fmaxf(m, __shfl_xor_sync(0xFFFFFFFFu, m, o));
    if ((threadIdx.x & 31) == 0) s_red[threadIdx.x >> 5] = m;
    __syncthreads();
    if (threadIdx.x == 0) {
        float r = s_red[0];
#pragma unroll
        for (int k = 1; k < 8; k++) r = fmaxf(r, s_red[k]);
        g_wmax_bits = __float_as_uint(r);
        s_ws = __fdiv_rn(r, 127.0f);   // match jnp: max/qmax, IEEE divide
    }
    __syncthreads();
    float ws = s_ws;
    // mma fragments for co 0-15
    for (int idx = threadIdx.x; idx < 9 * 2 * 32; idx += blockDim.x) {
        int lane = idx & 31;
        int nt   = (idx >> 5) & 1;
        int tap  = idx >> 6;
        int ki = tap / 3, kj = tap % 3;
        int co = nt * 8 + (lane >> 2);
        int cb = (lane & 3) * 4;
        int w0 = 0, w1 = 0;
#pragma unroll
        for (int kk = 0; kk < 4; kk++) {
            float v0 = wgt[((co * C_ + (cb + kk)) * 3 + ki) * 3 + kj];
            float v1 = wgt[((co * C_ + (16 + cb + kk)) * 3 + ki) * 3 + kj];
            int q0 = (int)rintf(__fdiv_rn(v0, ws));   // round-half-even
            int q1 = (int)rintf(__fdiv_rn(v1, ws));
            q0 = max(-127, min(127, q0));
            q1 = max(-127, min(127, q1));
            w0 |= (q0 & 0xFF) << (8 * kk);
            w1 |= (q1 & 0xFF) << (8 * kk);
        }
        g_qwm[idx] = make_int2(w0, w1);
    }
    // dp4a packed words for co 16-31
    for (int idx = threadIdx.x; idx < 9 * 8 * 16; idx += blockDim.x) {
        int co  = 16 + (idx & 15);
        int cg  = (idx >> 4) & 7;
        int tap = idx >> 7;
        int ki = tap / 3, kj = tap % 3;
        int word = 0;
#pragma unroll
        for (int k = 0; k < 4; k++) {
            float v = wgt[((co * C_ + (cg * 4 + k)) * 3 + ki) * 3 + kj];
            int q = (int)rintf(__fdiv_rn(v, ws));
            q = max(-127, min(127, q));
            word |= (q & 0xFF) << (8 * k);
        }
        g_qwd[idx] = word;
    }
}

// -------- 1: max|x|, 4x batched loads, ONE atomic per block --------
// (9472 same-address atomics serialize at L2 ~27cyc/op; smem reduce -> 1184.)
__global__ void k_xmax(const float4* __restrict__ x, int n4) {
    __shared__ float s_red[8];
    int stride = gridDim.x * blockDim.x;
    int i = blockIdx.x * blockDim.x + threadIdx.x;
    float m0 = 0.f, m1 = 0.f, m2 = 0.f, m3 = 0.f;
    for (; i + 3 * stride < n4; i += 4 * stride) {
        float4 a = x[i];
        float4 b = x[i + stride];
        float4 c = x[i + 2 * stride];
        float4 d = x[i + 3 * stride];
        m0 = fmaxf(m0, fmaxf(fmaxf(fabsf(a.x), fabsf(a.y)),
                             fmaxf(fabsf(a.z), fabsf(a.w))));
        m1 = fmaxf(m1, fmaxf(fmaxf(fabsf(b.x), fabsf(b.y)),
                             fmaxf(fabsf(b.z), fabsf(b.w))));
        m2 = fmaxf(m2, fmaxf(fmaxf(fabsf(c.x), fabsf(c.y)),
                             fmaxf(fabsf(c.z), fabsf(c.w))));
        m3 = fmaxf(m3, fmaxf(fmaxf(fabsf(d.x), fabsf(d.y)),
                             fmaxf(fabsf(d.z), fabsf(d.w))));
    }
    for (; i < n4; i += stride) {
        float4 a = x[i];
        m0 = fmaxf(m0, fmaxf(fmaxf(fabsf(a.x), fabsf(a.y)),
                             fmaxf(fabsf(a.z), fabsf(a.w))));
    }
    float m = fmaxf(fmaxf(m0, m1), fmaxf(m2, m3));
#pragma unroll
    for (int o = 16; o; o >>= 1)
        m = fmaxf(m, __shfl_xor_sync(0xFFFFFFFFu, m, o));
    if ((threadIdx.x & 31) == 0) s_red[threadIdx.x >> 5] = m;
    __syncthreads();
    if (threadIdx.x == 0) {
        float r = s_red[0];
#pragma unroll
        for (int k = 1; k < 8; k++) r = fmaxf(r, s_red[k]);
        atomicMax(&g_xmax_bits, __float_as_uint(r));  // r >= 0: bits monotone
    }
}

// -------- 2: quantize x into padded NHWC int8, one block per (b,h) row.
// ALL 32 channel loads front-batched into registers (MLP=32) before arithmetic
// (the cg-interleaved version measured 34.5us latency-bound at 28 regs).
__global__ void __launch_bounds__(W_) k_qx(const float* __restrict__ x) {
    int b = blockIdx.x / H_;
    int h = blockIdx.x - b * H_;
    int w = threadIdx.x;           // 0..223
    float xs = __fdiv_rn(__uint_as_float(g_xmax_bits), 127.0f);

    const float* px = x + ((b * C_) * H_ + h) * W_ + w;
    float v[C_];
#pragma unroll
    for (int c = 0; c < C_; c++)
        v[c] = px[c * H_ * W_];    // 32 independent coalesced LDGs

    int word[NW_];
#pragma unroll
    for (int cg = 0; cg < NW_; cg++) {
        int wd = 0;
#pragma unroll
        for (int k = 0; k < 4; k++) {
            int q = (int)rintf(__fdiv_rn(v[cg * 4 + k], xs));
            q = max(-127, min(127, q));
            wd |= (q & 0xFF) << (8 * k);
        }
        word[cg] = wd;
    }
    int4* dst = (int4*)(g_xq + ((b * HP_ + h + 1) * WP_ + (w + 1)) * NW_);
    dst[0] = make_int4(word[0], word[1], word[2], word[3]);
    dst[1] = make_int4(word[4], word[5], word[6], word[7]);
    if (w < 2) {
        int wp = (w == 0) ? 0 : (WP_ - 1);
        int4* pz = (int4*)(g_xq + ((b * HP_ + h + 1) * WP_ + wp) * NW_);
        pz[0] = make_int4(0, 0, 0, 0);
        pz[1] = make_int4(0, 0, 0, 0);
    }
    if (h == 0 || h == H_ - 1) {
        int hp = (h == 0) ? 0 : (HP_ - 1);
        int4* pr = (int4*)(g_xq + (b * HP_ + hp) * WP_ * NW_);
        const int row4 = (WP_ * NW_) / 4;
        for (int i = w; i < row4; i += W_)
            pr[i] = make_int4(0, 0, 0, 0);
    }
}

// -------- mma helpers --------
__device__ __forceinline__ void ldsm_x4(uint32_t* r, uint32_t saddr) {
    asm volatile(
        "ldmatrix.sync.aligned.m8n8.x4.shared.b16 {%0,%1,%2,%3}, [%4];"
        : "=r"(r[0]), "=r"(r[1]), "=r"(r[2]), "=r"(r[3]) : "r"(saddr));
}
__device__ __forceinline__ void mma_s8(int* d, const uint32_t* a,
                                       uint32_t b0, uint32_t b1) {
    asm volatile(
        "mma.sync.aligned.m16n8k32.row.col.s32.s8.s8.s32 "
        "{%0,%1,%2,%3}, {%4,%5,%6,%7}, {%8,%9}, {%0,%1,%2,%3};"
        : "+r"(d[0]), "+r"(d[1]), "+r"(d[2]), "+r"(d[3])
        : "r"(a[0]), "r"(a[1]), "r"(a[2]), "r"(a[3]), "r"(b0), "r"(b1));
}

// -------- 3: HYBRID conv: tensor pipe (mma, co 0-15) + fma pipe (dp4a, co 16-31)
// run concurrently. Legacy IMMA measured 282 MAC/cyc/SM (tensor 82% busy, all
// else idle in R11); dp4a adds an independent 256 MAC/cyc/SM on the fma pipe.
// smem x swizzle: word (pix,cg) at pix*8 + (pix>>2)*4 + cg; conflict-free for
// both ldmatrix phases and int4 dp4a loads (8 consecutive pixels hit bank-quads
// {0,8,16,24,4,12,20,28}).
#define ROW_WORDS 2036   // max swizzled word = 2031; pad to %4==0

__global__ void __launch_bounds__(224, 2) k_conv(const float* __restrict__ bias,
                                                 float* __restrict__ out) {
    __shared__ __align__(16) int  s_x[3 * ROW_WORDS];
    __shared__ __align__(16) int2 s_wm[9 * 2 * 32];
    __shared__ __align__(16) int  s_wd[9 * 8 * 16];
    __shared__ float s_bias[C_];

    int tid = threadIdx.x;
    int b = blockIdx.x / H_;
    int h = blockIdx.x - b * H_;
    int wid  = tid >> 5;
    int lane = tid & 31;

    // weights: s_wm 288 int4 + s_wd 288 int4, coalesced
    {
        const int4* wsrc = (const int4*)g_qwm;
        int4* wdst = (int4*)s_wm;
        for (int i = tid; i < (9 * 2 * 32 * 2) / 4; i += 224) wdst[i] = wsrc[i];
        const int4* dsrc = (const int4*)g_qwd;
        int4* ddst = (int4*)s_wd;
        for (int i = tid; i < (9 * 8 * 16) / 4; i += 224) ddst[i] = dsrc[i];
    }
    if (tid < C_) s_bias[tid] = bias[tid];

    // load 3 padded input rows (h, h+1, h+2 in padded coords), int4 both sides
    {
        const int4* src = (const int4*)(g_xq + (b * HP_ + h) * WP_ * NW_);
        const int row4 = (WP_ * NW_) / 4;              // 452 int4 per row
        for (int i = tid; i < 3 * row4; i += 224) {
            int r  = i / row4;
            int i4 = i - r * row4;
            int pix = i4 >> 1, half = i4 & 1;
            *(int4*)(s_x + r * ROW_WORDS + pix * 8 + (pix >> 2) * 4 + half * 4) =
                src[i];
        }
    }
    __syncthreads();

    // mma lane addresses (verified R11): matrix i <- lanes 8i..8i+7;
    // grp0 pix0-7/ch0-15, grp1 pix8-15/ch0-15, grp2 pix0-7/ch16-31, grp3 pix8-15/ch16-31
    uint32_t sx_base = (uint32_t)__cvta_generic_to_shared(s_x);
    int grp  = lane >> 3;
    int row8 = lane & 7;
    int halfg = grp >> 1;
    int rofs = (grp & 1) << 3;
    uint32_t a_addr[2][3];
#pragma unroll
    for (int mt = 0; mt < 2; mt++) {
#pragma unroll
        for (int kj = 0; kj < 3; kj++) {
            int pix = 32 * wid + 16 * mt + kj + row8 + rofs;
            int word = pix * 8 + (pix >> 2) * 4 + halfg * 4;
            a_addr[mt][kj] = sx_base + word * 4;
        }
    }

    // dp4a mapping: 4 pixels (wt+56jj), 4 co (16 + cob4 + r)
    int wt   = tid % 56;
    int cob4 = (tid / 56) * 4;

    int acc_m[2][2][4];
    int acc_d[4][4];
#pragma unroll
    for (int mt = 0; mt < 2; mt++)
#pragma unroll
        for (int nt = 0; nt < 2; nt++)
#pragma unroll
            for (int r = 0; r < 4; r++) acc_m[mt][nt][r] = 0;
#pragma unroll
    for (int jj = 0; jj < 4; jj++)
#pragma unroll
        for (int r = 0; r < 4; r++) acc_d[jj][r] = 0;

#pragma unroll
    for (int ki = 0; ki < 3; ki++) {
        uint32_t kofs = ki * (ROW_WORDS * 4);
        const int* xr = s_x + ki * ROW_WORDS;
#pragma unroll
        for (int kj = 0; kj < 3; kj++) {
            int tap = ki * 3 + kj;
            // ---- tensor-pipe half (co 0-15) ----
            int2 bf0 = s_wm[(tap * 2 + 0) * 32 + lane];
            int2 bf1 = s_wm[(tap * 2 + 1) * 32 + lane];
            uint32_t A0[4], A1[4];
            ldsm_x4(A0, a_addr[0][kj] + kofs);
            ldsm_x4(A1, a_addr[1][kj] + kofs);
            mma_s8(acc_m[0][0], A0, (uint32_t)bf0.x, (uint32_t)bf0.y);
            mma_s8(acc_m[0][1], A0, (uint32_t)bf1.x, (uint32_t)bf1.y);
            mma_s8(acc_m[1][0], A1, (uint32_t)bf0.x, (uint32_t)bf0.y);
            mma_s8(acc_m[1][1], A1, (uint32_t)bf1.x, (uint32_t)bf1.y);
            // ---- fma-pipe half (co 16-31) ----
#pragma unroll
            for (int half = 0; half < 2; half++) {
                int4 xh[4];
#pragma unroll
                for (int jj = 0; jj < 4; jj++) {
                    int pix = wt + 56 * jj + kj;
                    xh[jj] = *(const int4*)(xr + pix * 8 + (pix >> 2) * 4 + half * 4);
                }
#pragma unroll
                for (int cgl = 0; cgl < 4; cgl++) {
                    int cg = half * 4 + cgl;
                    // lanes of a 56-thread group share cob4 -> broadcast load
                    int4 wq = *(const int4*)(s_wd + (tap * 8 + cg) * 16 + cob4);
#pragma unroll
                    for (int jj = 0; jj < 4; jj++) {
                        int xw = (cgl == 0) ? xh[jj].x : (cgl == 1) ? xh[jj].y
                               : (cgl == 2) ? xh[jj].z : xh[jj].w;
                        acc_d[jj][0] = __dp4a(xw, wq.x, acc_d[jj][0]);
                        acc_d[jj][1] = __dp4a(xw, wq.y, acc_d[jj][1]);
                        acc_d[jj][2] = __dp4a(xw, wq.z, acc_d[jj][2]);
                        acc_d[jj][3] = __dp4a(xw, wq.w, acc_d[jj][3]);
                    }
                }
            }
        }
    }

    float xs = __fdiv_rn(__uint_as_float(g_xmax_bits), 127.0f);
    float ws = __fdiv_rn(__uint_as_float(g_wmax_bits), 127.0f);
    float sc = xs * ws;

    // mma epilogue (co 0-15): c0 (pix base+lane/4, co nt*8+(lane%4)*2), c1 co+1,
    // c2/c3 pix+8
#pragma unroll
    for (int mt = 0; mt < 2; mt++) {
        int pix0 = 32 * wid + 16 * mt + (lane >> 2);
#pragma unroll
        for (int nt = 0; nt < 2; nt++) {
            int co0 = nt * 8 + (lane & 3) * 2;
            float b0f = s_bias[co0], b1f = s_bias[co0 + 1];
            float* o00 = out + ((b * C_ + co0) * H_ + h) * W_;
            float* o01 = o00 + H_ * W_;
            o00[pix0]     = (float)acc_m[mt][nt][0] * sc + b0f;
            o01[pix0]     = (float)acc_m[mt][nt][1] * sc + b1f;
            o00[pix0 + 8] = (float)acc_m[mt][nt][2] * sc + b0f;
            o01[pix0 + 8] = (float)acc_m[mt][nt][3] * sc + b1f;
        }
    }
    // dp4a epilogue (co 16-31): warp spans contiguous pixels -> coalesced
#pragma unroll
    for (int r = 0; r < 4; r++) {
        int co = 16 + cob4 + r;
        float bb = s_bias[co];
        float* po = out + ((b * C_ + co) * H_ + h) * W_;
#pragma unroll
        for (int jj = 0; jj < 4; jj++)
            po[wt + 56 * jj] = (float)acc_d[jj][r] * sc + bb;
    }
}

// -------- launch --------
extern "C" void kernel_launch(void* const* d_in, const int* in_sizes, int n_in,
                              void* d_out, int out_size) {
    const float* x    = (const float*)d_in[0];   // [8,32,224,224]
    const float* w    = (const float*)d_in[1];   // [32,32,3,3]
    const float* bias = (const float*)d_in[2];   // [32]
    float* out = (float*)d_out;                  // [8,32,224,224]

    k_prepqw<<<1, 256>>>(w, C_ * C_ * 9);        // zero xmax + wmax + pack weights

    int n4 = (B_ * C_ * H_ * W_) / 4;            // exactly divisible
    k_xmax<<<1184, 256>>>((const float4*)x, n4); // 148 SMs x 8: exact waves

    k_qx<<<B_ * H_, W_>>>(x);

    k_conv<<<B_ * H_, 224>>>(bias, out);
}